// round 17
// baseline (speedup 1.0000x reference)
#include <cuda_runtime.h>

#define SEQ_LEN   8192
#define HIDDEN    1024
#define H2        512                 // f32x2 (ull) per full row
#define HH        256                 // ull per half row
#define H4        256                 // float4 per row
#define NUM_SPANS 4096
#define MAX_W     32
#define SPB       16                  // sorted spans per group
#define WCAP      96                  // max union-window rows (fast path)
#define WPAD      (WCAP + 4)          // zero-padded table rows
#define SCORE_BLOCKS 256              // 1024-thr blocks: 32 rows each

__device__ float g_scores[SEQ_LEN];
__device__ int   g_sorted[NUM_SPANS];

typedef unsigned long long ull;

__device__ __forceinline__ void ffma2(ull& d, ull a, ull b) {
    asm("fma.rn.f32x2 %0, %1, %2, %0;" : "+l"(d) : "l"(a), "l"(b));
}
__device__ __forceinline__ ull packf2(float lo, float hi) {
    ull r; asm("mov.b64 %0, {%1, %2};" : "=l"(r) : "f"(lo), "f"(hi)); return r;
}

// ---------------- Kernel 1: scores (blocks 0..255) + full sort (block 256) -
__global__ __launch_bounds__(1024) void setup_kernel(
        const float* __restrict__ emb,
        const float* __restrict__ attn_w,
        const float* __restrict__ attn_b,
        const int*   __restrict__ starts) {
    __shared__ int s_cnt[SEQ_LEN];        // 32 KB
    __shared__ int s_wtot[32];

    if (blockIdx.x < SCORE_BLOCKS) {
        int warp = (blockIdx.x * 1024 + threadIdx.x) >> 5;
        int lane = threadIdx.x & 31;

        const float4* row = (const float4*)(emb) + (size_t)warp * H4;
        const float4* wv  = (const float4*)(attn_w);

        float acc = 0.0f;
#pragma unroll
        for (int j = 0; j < H4 / 32; j++) {
            float4 a = row[j * 32 + lane];
            float4 c = wv [j * 32 + lane];
            acc += a.x * c.x + a.y * c.y + a.z * c.z + a.w * c.w;
        }
#pragma unroll
        for (int off = 16; off; off >>= 1)
            acc += __shfl_xor_sync(0xffffffffu, acc, off);

        if (lane == 0) g_scores[warp] = acc + attn_b[0];
        return;
    }

    const int t = threadIdx.x;            // 1024 threads
    for (int i = t; i < SEQ_LEN; i += 1024) s_cnt[i] = 0;
    __syncthreads();

    for (int j = t; j < NUM_SPANS; j += 1024)
        atomicAdd(&s_cnt[starts[j]], 1);
    __syncthreads();

    const int base = t * 8;
    int loc[8];
    int tsum = 0;
#pragma unroll
    for (int i = 0; i < 8; i++) { loc[i] = tsum; tsum += s_cnt[base + i]; }

    const int lane = t & 31, wid = t >> 5;
    int x = tsum;
#pragma unroll
    for (int off = 1; off < 32; off <<= 1) {
        int y = __shfl_up_sync(0xffffffffu, x, off);
        if (lane >= off) x += y;
    }
    if (lane == 31) s_wtot[wid] = x;
    __syncthreads();
    if (wid == 0) {
        int s = s_wtot[lane];
#pragma unroll
        for (int off = 1; off < 32; off <<= 1) {
            int y = __shfl_up_sync(0xffffffffu, s, off);
            if (lane >= off) s += y;
        }
        s_wtot[lane] = s;
    }
    __syncthreads();

    int excl = x - tsum + (wid ? s_wtot[wid - 1] : 0);
#pragma unroll
    for (int i = 0; i < 8; i++) s_cnt[base + i] = excl + loc[i];
    __syncthreads();

    for (int j = t; j < NUM_SPANS; j += 1024) {
        int p = atomicAdd(&s_cnt[starts[j]], 1);
        g_sorted[p] = j;
    }
}

// ---- Kernel 2: 16 spans/group, half-hidden, 256 thr ----------------------
__global__ __launch_bounds__(256) void span_main(
        const float* __restrict__ emb,
        const int*   __restrict__ starts,
        const int*   __restrict__ ends,
        float*       __restrict__ out) {
    __shared__ ull s_wt[WPAD][SPB];       // zero-padded weight table, 12.5 KB
    __shared__ ull s_wp[SPB][MAX_W];      // per-span weights (slow path), 4 KB
    __shared__ int s_s[SPB], s_wd[SPB], s_j[SPB];

    const int tid  = threadIdx.x;         // one f32x2 column of the half-row
    const int wid  = tid >> 5;            // 0..7
    const int lane = tid & 31;
    const int grp  = blockIdx.x >> 1;     // span group (16 sorted spans)
    const int h    = blockIdx.x & 1;      // hidden half

    // ---- softmax: 8 warps x 2 slots each ----
#pragma unroll
    for (int rep = 0; rep < 2; rep++) {
        int slot = wid * 2 + rep;
        int j = g_sorted[grp * SPB + slot];
        int s = starts[j];
        int W = ends[j] - s;              // width-1 in [0,31]
        float sc = (lane <= W) ? g_scores[s + lane] : -1e9f;
        float m = sc;
#pragma unroll
        for (int off = 16; off; off >>= 1)
            m = fmaxf(m, __shfl_xor_sync(0xffffffffu, m, off));
        float p = __expf(sc - m);
        float sum = p;
#pragma unroll
        for (int off = 16; off; off >>= 1)
            sum += __shfl_xor_sync(0xffffffffu, sum, off);
        float wgt = p / sum;
        s_wp[slot][lane] = packf2(wgt, wgt);
        if (lane == 0) { s_s[slot] = s; s_wd[slot] = W; s_j[slot] = j; }
    }
    // zero the padded table: WPAD*SPB = 1600 ull / 256 threads
    for (int i = tid; i < WPAD * SPB; i += 256) ((ull*)s_wt)[i] = 0ull;
    __syncthreads();

    const int rmin = s_s[0];              // sorted by start
    int rmax = s_s[0] + s_wd[0];
#pragma unroll
    for (int k = 1; k < SPB; k++) rmax = max(rmax, s_s[k] + s_wd[k]);
    const int win = rmax - rmin + 1;

    const ull* colp = (const ull*)(emb) + h * HH + tid;   // + r*H2 per row
    ull*       ob   = (ull*)(out);

    if (win <= WCAP) {
        // scatter weights into the zero-padded table (2 slots per warp)
#pragma unroll
        for (int rep = 0; rep < 2; rep++) {
            int slot = wid * 2 + rep;
            if (lane <= s_wd[slot])
                s_wt[s_s[slot] - rmin + lane][slot] = s_wp[slot][lane];
        }
        __syncthreads();

        ull acc[SPB];
#pragma unroll
        for (int k = 0; k < SPB; k++) acc[k] = 0ull;

        // depth-1 value prefetch (clamped; zero weights => exact no-op)
        ull v = colp[(size_t)rmin * H2];

        for (int rw = 0; rw < win; rw++) {
            ull vn = colp[(size_t)min(rmin + rw + 1, SEQ_LEN - 1) * H2];
            const ulonglong2* wr = (const ulonglong2*)s_wt[rw];
            // spans 0..7
            {
                ulonglong2 w01 = wr[0], w23 = wr[1], w45 = wr[2], w67 = wr[3];
                ffma2(acc[0], w01.x, v); ffma2(acc[1], w01.y, v);
                ffma2(acc[2], w23.x, v); ffma2(acc[3], w23.y, v);
                ffma2(acc[4], w45.x, v); ffma2(acc[5], w45.y, v);
                ffma2(acc[6], w67.x, v); ffma2(acc[7], w67.y, v);
            }
            // spans 8..15
            {
                ulonglong2 w89 = wr[4], wab = wr[5], wcd = wr[6], wef = wr[7];
                ffma2(acc[8],  w89.x, v); ffma2(acc[9],  w89.y, v);
                ffma2(acc[10], wab.x, v); ffma2(acc[11], wab.y, v);
                ffma2(acc[12], wcd.x, v); ffma2(acc[13], wcd.y, v);
                ffma2(acc[14], wef.x, v); ffma2(acc[15], wef.y, v);
            }
            v = vn;
        }

        // ---- epilogue: attn_out + start/end copies ----
#pragma unroll
        for (int k = 0; k < SPB; k++) {
            int obase = s_j[k] * (3 * H2) + h * HH + tid;
            int s0 = s_s[k];
            ob[obase + 2 * H2] = acc[k];
            ob[obase]          = colp[(size_t)s0 * H2];
            ob[obase + H2]     = colp[(size_t)(s0 + s_wd[k]) * H2];
        }
    } else {
        // ---- rare slow path: sweep each span in turn ----
        for (int k = 0; k < SPB; k++) {
            int s0 = s_s[k], W = s_wd[k];
            int obase = s_j[k] * (3 * H2) + h * HH + tid;
            const ull* bp = colp + (size_t)s0 * H2;
            ull acc = 0ull;
            for (int r = 0; r <= W; r++) {
                ull w2 = s_wp[k][r];       // broadcast LDS
                ffma2(acc, w2, bp[(size_t)r * H2]);
            }
            ob[obase + 2 * H2] = acc;
            ob[obase]          = bp[0];
            ob[obase + H2]     = bp[(size_t)W * H2];
        }
    }
}

extern "C" void kernel_launch(void* const* d_in, const int* in_sizes, int n_in,
                              void* d_out, int out_size) {
    const float* emb    = (const float*)d_in[0];
    const int*   starts = (const int*)  d_in[1];
    const int*   ends   = (const int*)  d_in[2];
    const float* attn_w = (const float*)d_in[3];
    const float* attn_b = (const float*)d_in[4];
    float*       out    = (float*)d_out;

    setup_kernel<<<SCORE_BLOCKS + 1, 1024>>>(emb, attn_w, attn_b, starts);
    span_main<<<(NUM_SPANS / SPB) * 2, 256>>>(emb, starts, ends, out);
}